// round 2
// baseline (speedup 1.0000x reference)
#include <cuda_runtime.h>

#define N_NODES 4096
#define HIDDEN  64
#define N_REL   8
#define N_LAYERS 2
#define NH (N_NODES * HIDDEN)

typedef unsigned long long ull;

// d = a * b + d, packed 2x fp32 (sm_100+ FFMA2; not emitted by ptxas from C++)
#define FFMA2(d, a, b) \
    asm("fma.rn.f32x2 %0, %1, %2, %3;" : "=l"(d) : "l"(a), "l"(b), "l"(d))

// Scratch (device globals — no allocation allowed)
__device__ float g_h[2][NH];        // ping-pong hidden state
__device__ float g_Y[N_REL][NH];    // per-relation h @ w_rel[l,r]
__device__ float g_S[NH];           // h @ w_self[l]
__device__ float g_part[N_REL][NH]; // split-K partials

// ---------------------------------------------------------------------------
// init: copy node_embed[:4096] into g_h[0]
// ---------------------------------------------------------------------------
__global__ void copy_init_kernel(float* __restrict__ dst, const float* __restrict__ src) {
    int i = blockIdx.x * blockDim.x + threadIdx.x;
    if (i < NH / 4) ((float4*)dst)[i] = ((const float4*)src)[i];
}

// ---------------------------------------------------------------------------
// compute Y_r = h @ w_rel[l,r]  (blockIdx.y = 0..7)  and  S = h @ w_self[l]
// (blockIdx.y = 8). Block handles a 64-row m-tile.
// ---------------------------------------------------------------------------
__global__ void __launch_bounds__(256) compute_ys_kernel(
    const float* __restrict__ h,
    const float* __restrict__ w_self,
    const float* __restrict__ w_rel,
    int layer, float* __restrict__ Y, float* __restrict__ S)
{
    __shared__ float Ws[HIDDEN * HIDDEN];
    __shared__ float Hs[64 * HIDDEN];

    int m0 = blockIdx.x * 64;
    int wi = blockIdx.y;
    const float* W = (wi < N_REL)
        ? (w_rel + ((size_t)layer * N_REL + wi) * HIDDEN * HIDDEN)
        : (w_self + (size_t)layer * HIDDEN * HIDDEN);
    float* out = (wi < N_REL)
        ? (Y + (size_t)wi * NH + (size_t)m0 * HIDDEN)
        : (S + (size_t)m0 * HIDDEN);

    int tid = threadIdx.x;
    const float4* Wg = (const float4*)W;
    const float4* Hg = (const float4*)(h + (size_t)m0 * HIDDEN);
    for (int i = tid; i < 1024; i += 256) {
        ((float4*)Ws)[i] = Wg[i];
        ((float4*)Hs)[i] = Hg[i];
    }
    __syncthreads();

    int tx = tid & 15, ty = tid >> 4;
    int e0 = tx * 4;
    #pragma unroll
    for (int mi = 0; mi < 4; mi++) {
        int m = ty * 4 + mi;
        float4 acc = make_float4(0.f, 0.f, 0.f, 0.f);
        #pragma unroll
        for (int d = 0; d < HIDDEN; d++) {
            float hv = Hs[m * HIDDEN + d];
            float4 wv = *(const float4*)&Ws[d * HIDDEN + e0];
            acc.x = fmaf(hv, wv.x, acc.x);
            acc.y = fmaf(hv, wv.y, acc.y);
            acc.z = fmaf(hv, wv.z, acc.z);
            acc.w = fmaf(hv, wv.w, acc.w);
        }
        *(float4*)&out[m * HIDDEN + e0] = acc;
    }
}

// ---------------------------------------------------------------------------
// Main GEMM, split-K over relations, f32x2 packed FMA:
//   part[r][n][e] = sum_m adj[r][n][m] * Y[r][m][e]
// Block tile: 64(n) x 64(e), TK=16, 256 threads, 4x4 micro-tile.
// As stored DUPLICATED as float2(v,v) so FFMA2's "a" operand pairs come
// straight from LDS with no MOV/PRMT duplication cost.
// Grid: (64 n-tiles, 8 relations) = 512 blocks.
// ---------------------------------------------------------------------------
#define TK 16
__global__ void __launch_bounds__(256) gemm_part_kernel(
    const float* __restrict__ adj,
    const float* __restrict__ Yall,
    float* __restrict__ part)
{
    __shared__ float2 As2[TK][66];   // As2[k][n_local] = (v, v); 66 pad
    __shared__ float  Bs[TK][68];    // Bs[k][e]; 68 pad

    int n0 = blockIdx.x * 64;
    int r  = blockIdx.y;
    const float* A = adj  + (size_t)r * N_NODES * N_NODES;
    const float* B = Yall + (size_t)r * NH;

    int tid = threadIdx.x;
    int tx = tid & 15, ty = tid >> 4;
    int arow = tid >> 2,  acol = (tid & 3) * 4;    // A loader: 64 rows x 16 k
    int brow = tid >> 4,  bcol = (tid & 15) * 4;   // B loader: 16 k x 64 e

    const float* Aptr = A + (size_t)(n0 + arow) * N_NODES + acol;
    const float* Bptr = B + (size_t)brow * HIDDEN + bcol;

    // acc[i][j2]: packed pair (c[i][2*j2], c[i][2*j2+1])
    ull acc[4][2];
    #pragma unroll
    for (int i = 0; i < 4; i++) { acc[i][0] = 0ULL; acc[i][1] = 0ULL; }

    for (int mt = 0; mt < N_NODES; mt += TK) {
        float4 av = *(const float4*)(Aptr + mt);
        float4 bv = *(const float4*)(Bptr + (size_t)mt * HIDDEN);
        __syncthreads();
        As2[acol + 0][arow] = make_float2(av.x, av.x);
        As2[acol + 1][arow] = make_float2(av.y, av.y);
        As2[acol + 2][arow] = make_float2(av.z, av.z);
        As2[acol + 3][arow] = make_float2(av.w, av.w);
        *(float4*)&Bs[brow][bcol] = bv;
        __syncthreads();
        #pragma unroll
        for (int k = 0; k < TK; k++) {
            ulonglong2 a01 = *(const ulonglong2*)&As2[k][ty * 4];
            ulonglong2 a23 = *(const ulonglong2*)&As2[k][ty * 4 + 2];
            ulonglong2 b01 = *(const ulonglong2*)&Bs[k][tx * 4];
            FFMA2(acc[0][0], a01.x, b01.x);
            FFMA2(acc[0][1], a01.x, b01.y);
            FFMA2(acc[1][0], a01.y, b01.x);
            FFMA2(acc[1][1], a01.y, b01.y);
            FFMA2(acc[2][0], a23.x, b01.x);
            FFMA2(acc[2][1], a23.x, b01.y);
            FFMA2(acc[3][0], a23.y, b01.x);
            FFMA2(acc[3][1], a23.y, b01.y);
        }
    }

    float* P = part + (size_t)r * NH;
    #pragma unroll
    for (int i = 0; i < 4; i++) {
        int row = n0 + ty * 4 + i;
        float2 f0 = *(float2*)&acc[i][0];
        float2 f1 = *(float2*)&acc[i][1];
        float4 v = make_float4(f0.x, f0.y, f1.x, f1.y);
        *(float4*)&P[(size_t)row * HIDDEN + tx * 4] = v;
    }
}

// ---------------------------------------------------------------------------
// finish: h_next = relu(S + sum_r part[r])
// ---------------------------------------------------------------------------
__global__ void finish_kernel(const float* __restrict__ S,
                              const float* __restrict__ part,
                              float* __restrict__ hn)
{
    int i = blockIdx.x * blockDim.x + threadIdx.x;
    if (i < NH) {
        float v = S[i];
        #pragma unroll
        for (int r = 0; r < N_REL; r++) v += part[(size_t)r * NH + i];
        hn[i] = fmaxf(v, 0.f);
    }
}

// ---------------------------------------------------------------------------
// gather: out[k][e] = (id < 4096) ? h[id][e] : 0   (id==4096 is the pad row)
// ---------------------------------------------------------------------------
__global__ void gather_kernel(const float* __restrict__ h,
                              const int* __restrict__ ids,
                              float* __restrict__ out)
{
    int k = blockIdx.x;          // 0..2047 keyword slots
    int e = threadIdx.x;         // 0..63
    int id = ids[k];
    float v = (id < N_NODES) ? h[(size_t)id * HIDDEN + e] : 0.f;
    out[(size_t)k * HIDDEN + e] = v;
}

// ---------------------------------------------------------------------------
extern "C" void kernel_launch(void* const* d_in, const int* in_sizes, int n_in,
                              void* d_out, int out_size)
{
    const float* node_embed  = (const float*)d_in[0];
    const float* w_self      = (const float*)d_in[1];
    const float* w_rel       = (const float*)d_in[2];
    const float* rel_adj     = (const float*)d_in[3];
    const int*   keyword_ids = (const int*)d_in[4];
    float* out = (float*)d_out;

    float *h_base, *y_base, *s_base, *p_base;
    cudaGetSymbolAddress((void**)&h_base, g_h);
    cudaGetSymbolAddress((void**)&y_base, g_Y);
    cudaGetSymbolAddress((void**)&s_base, g_S);
    cudaGetSymbolAddress((void**)&p_base, g_part);

    copy_init_kernel<<<NH / 4 / 256, 256>>>(h_base, node_embed);

    for (int l = 0; l < N_LAYERS; l++) {
        float* hc = h_base + (size_t)(l & 1) * NH;
        float* hn = h_base + (size_t)((l + 1) & 1) * NH;
        compute_ys_kernel<<<dim3(64, 9), 256>>>(hc, w_self, w_rel, l, y_base, s_base);
        gemm_part_kernel<<<dim3(64, N_REL), 256>>>(rel_adj, y_base, p_base);
        finish_kernel<<<NH / 256, 256>>>(s_base, p_base, hn);
    }

    // after 2 layers, final h is back in g_h[0]
    gather_kernel<<<2048, 64>>>(h_base, keyword_ids, out);
}

// round 4
// speedup vs baseline: 2.8851x; 2.8851x over previous
#include <cuda_runtime.h>
#include <cuda_bf16.h>
#include <cstdint>

#define N_NODES 4096
#define HIDDEN  64
#define N_REL   8
#define N_LAYERS 2
#define NH (N_NODES * HIDDEN)

// ---------------------------------------------------------------- helpers
__device__ __forceinline__ uint32_t smem_u32(const void* p) {
    uint32_t a;
    asm("{ .reg .u64 t; cvta.to.shared.u64 t, %1; cvt.u32.u64 %0, t; }" : "=r"(a) : "l"(p));
    return a;
}

// pack two floats into bf16x2 (f_even -> low half)
#define CVT_BF16X2(d, f_even, f_odd) \
    asm("cvt.rn.bf16x2.f32 %0, %1, %2;" : "=r"(d) : "f"(f_odd), "f"(f_even))

#define LDSM4(r, addr) \
    asm volatile("ldmatrix.sync.aligned.m8n8.x4.shared.b16 {%0,%1,%2,%3}, [%4];" \
        : "=r"((r)[0]), "=r"((r)[1]), "=r"((r)[2]), "=r"((r)[3]) : "r"(addr))

#define MMA16816(c, a, b0, b1) \
    asm volatile("mma.sync.aligned.m16n8k16.row.col.f32.bf16.bf16.f32 " \
        "{%0,%1,%2,%3}, {%4,%5,%6,%7}, {%8,%9}, {%0,%1,%2,%3};" \
        : "+f"((c)[0]), "+f"((c)[1]), "+f"((c)[2]), "+f"((c)[3]) \
        : "r"((a)[0]), "r"((a)[1]), "r"((a)[2]), "r"((a)[3]), "r"(b0), "r"(b1))

// ---------------------------------------------------------------- scratch
__device__ float g_h[2][NH];
__device__ float g_S[NH];
__device__ float g_part[N_REL][NH];
__device__ __nv_bfloat16 g_Yth[N_REL][HIDDEN][N_NODES];  // Y^T hi  [r][e][m]
__device__ __nv_bfloat16 g_Ytl[N_REL][HIDDEN][N_NODES];  // Y^T lo

// ---------------------------------------------------------------- init copy
__global__ void copy_init_kernel(float* __restrict__ dst, const float* __restrict__ src) {
    int i = blockIdx.x * blockDim.x + threadIdx.x;
    if (i < NH / 4) ((float4*)dst)[i] = ((const float4*)src)[i];
}

// ---------------------------------------------------------------- Y / S
__global__ void __launch_bounds__(256) compute_ys_kernel(
    const float* __restrict__ h,
    const float* __restrict__ w_self,
    const float* __restrict__ w_rel,
    int layer,
    __nv_bfloat16* __restrict__ Yth,
    __nv_bfloat16* __restrict__ Ytl,
    float* __restrict__ S)
{
    __shared__ float Ws[HIDDEN * HIDDEN];
    __shared__ float Hs[64 * HIDDEN];

    int m0 = blockIdx.x * 64;
    int wi = blockIdx.y;
    const float* W = (wi < N_REL)
        ? (w_rel + ((size_t)layer * N_REL + wi) * HIDDEN * HIDDEN)
        : (w_self + (size_t)layer * HIDDEN * HIDDEN);

    int tid = threadIdx.x;
    const float4* Wg = (const float4*)W;
    const float4* Hg = (const float4*)(h + (size_t)m0 * HIDDEN);
    for (int i = tid; i < 1024; i += 256) {
        ((float4*)Ws)[i] = Wg[i];
        ((float4*)Hs)[i] = Hg[i];
    }
    __syncthreads();

    int tx = tid & 15, ty = tid >> 4;
    int e0 = tx * 4;
    #pragma unroll
    for (int mi = 0; mi < 4; mi++) {
        int m = ty * 4 + mi;
        float4 acc = make_float4(0.f, 0.f, 0.f, 0.f);
        #pragma unroll
        for (int d = 0; d < HIDDEN; d++) {
            float hv = Hs[m * HIDDEN + d];
            float4 wv = *(const float4*)&Ws[d * HIDDEN + e0];
            acc.x = fmaf(hv, wv.x, acc.x);
            acc.y = fmaf(hv, wv.y, acc.y);
            acc.z = fmaf(hv, wv.z, acc.z);
            acc.w = fmaf(hv, wv.w, acc.w);
        }
        int mg = m0 + m;
        if (wi < N_REL) {
            float v[4] = {acc.x, acc.y, acc.z, acc.w};
            #pragma unroll
            for (int j = 0; j < 4; j++) {
                size_t idx = ((size_t)wi * HIDDEN + (e0 + j)) * N_NODES + mg;
                __nv_bfloat16 hi = __float2bfloat16_rn(v[j]);
                float res = v[j] - __bfloat162float(hi);
                Yth[idx] = hi;
                Ytl[idx] = __float2bfloat16_rn(res);
            }
        } else {
            *(float4*)&S[(size_t)mg * HIDDEN + e0] = acc;
        }
    }
}

// ---------------------------------------------------------------- tensor GEMM (mma.sync)
// part[r][n][e] = sum_m adj[r][n][m] * Y_r[m][e]
// CTA tile 128(M=n) x 64(N=e), K-chunk 32, 8 warps in 4x2, warp tile 32x32.
// A = adj fp32 -> bf16 hi/lo split (3-term). B = Y^T hi/lo (already bf16).
#define KC 32
#define APAD 40   // row stride in bf16 elems (80 B) -> conflict-free ldmatrix

__global__ void __launch_bounds__(256) gemm_mma_kernel(
    const float* __restrict__ adj,
    const __nv_bfloat16* __restrict__ Yth,
    const __nv_bfloat16* __restrict__ Ytl,
    float* __restrict__ part)
{
    __shared__ __align__(16) __nv_bfloat16 Ah[128][APAD];
    __shared__ __align__(16) __nv_bfloat16 Al[128][APAD];
    __shared__ __align__(16) __nv_bfloat16 Bh[64][APAD];
    __shared__ __align__(16) __nv_bfloat16 Bl[64][APAD];

    const int tid  = threadIdx.x;
    const int lane = tid & 31;
    const int wid  = tid >> 5;
    const int warp_m = wid & 3;   // 4 m-tiles of 32
    const int warp_n = wid >> 2;  // 2 n-tiles of 32
    const int n0 = blockIdx.x * 128;
    const int r  = blockIdx.y;

    // ---- loader geometry ----
    const int arow = tid >> 1, aseg = tid & 1;                 // A: 128 rows x 2 half-rows
    const float* Abase = adj + ((size_t)r << 24)
                       + (size_t)(n0 + arow) * N_NODES + aseg * 16;
    const int brow = tid >> 2, bseg = tid & 3;                 // B: 64 rows x 4 segs of 8
    const size_t boff = ((size_t)r * HIDDEN + brow) * N_NODES + bseg * 8;
    const __nv_bfloat16* Bhg = Yth + boff;
    const __nv_bfloat16* Blg = Ytl + boff;

    // ---- ldmatrix per-lane addresses ----
    // A (16x16 tiles): t0-7 rows0-7 col0 | t8-15 rows8-15 col0 | t16-23 rows0-7 col8 | t24-31 rows8-15 col8
    const int a_r = warp_m * 32 + (lane & 15);
    const int a_c16 = (lane >> 4) * 16;                        // bytes (8 elems)
    const uint32_t ah_base = smem_u32(Ah) + a_r * (APAD * 2) + a_c16;
    const uint32_t al_base = smem_u32(Al) + a_r * (APAD * 2) + a_c16;
    // B (two n8k16 frags per x4): t0-7 n0-7 k0 | t8-15 n0-7 k8 | t16-23 n8-15 k0 | t24-31 n8-15 k8
    const int b_r = warp_n * 32 + (lane & 7) + ((lane >> 4) & 1) * 8;
    const int b_c16 = ((lane >> 3) & 1) * 16;                  // bytes
    const uint32_t bh_base = smem_u32(Bh) + b_r * (APAD * 2) + b_c16;
    const uint32_t bl_base = smem_u32(Bl) + b_r * (APAD * 2) + b_c16;

    float c[2][4][4];
    #pragma unroll
    for (int i = 0; i < 2; i++)
        #pragma unroll
        for (int j = 0; j < 4; j++)
            #pragma unroll
            for (int k = 0; k < 4; k++) c[i][j][k] = 0.f;

    float4 fA[4];
    uint4 sBh, sBl;

    // ---- prologue: load + convert + STS chunk 0 ----
    #pragma unroll
    for (int i = 0; i < 4; i++) fA[i] = *(const float4*)(Abase + i * 4);
    sBh = *(const uint4*)Bhg;
    sBl = *(const uint4*)Blg;
    {
        uint32_t hi[8], lo[8];
        #pragma unroll
        for (int p = 0; p < 4; p++) {
            float e0 = fA[p].x, o0 = fA[p].y, e1 = fA[p].z, o1 = fA[p].w;
            uint32_t h0, h1;
            CVT_BF16X2(h0, e0, o0);
            CVT_BF16X2(h1, e1, o1);
            hi[p * 2] = h0; hi[p * 2 + 1] = h1;
            float r0e = e0 - __uint_as_float(h0 << 16);
            float r0o = o0 - __uint_as_float(h0 & 0xffff0000u);
            float r1e = e1 - __uint_as_float(h1 << 16);
            float r1o = o1 - __uint_as_float(h1 & 0xffff0000u);
            uint32_t l0, l1;
            CVT_BF16X2(l0, r0e, r0o);
            CVT_BF16X2(l1, r1e, r1o);
            lo[p * 2] = l0; lo[p * 2 + 1] = l1;
        }
        *(uint4*)&Ah[arow][aseg * 16]     = make_uint4(hi[0], hi[1], hi[2], hi[3]);
        *(uint4*)&Ah[arow][aseg * 16 + 8] = make_uint4(hi[4], hi[5], hi[6], hi[7]);
        *(uint4*)&Al[arow][aseg * 16]     = make_uint4(lo[0], lo[1], lo[2], lo[3]);
        *(uint4*)&Al[arow][aseg * 16 + 8] = make_uint4(lo[4], lo[5], lo[6], lo[7]);
        *(uint4*)&Bh[brow][bseg * 8] = sBh;
        *(uint4*)&Bl[brow][bseg * 8] = sBl;
    }
    __syncthreads();

    #pragma unroll 1
    for (int it = 0; it < N_NODES / KC; ++it) {
        const bool last = (it == N_NODES / KC - 1);
        // prefetch next chunk into registers (overlaps with MMA below)
        if (!last) {
            const int mt = (it + 1) * KC;
            #pragma unroll
            for (int i = 0; i < 4; i++) fA[i] = *(const float4*)(Abase + mt + i * 4);
            sBh = *(const uint4*)(Bhg + mt);
            sBl = *(const uint4*)(Blg + mt);
        }

        // ---- MMA phase: 2 k16 steps ----
        #pragma unroll
        for (int ks = 0; ks < 2; ks++) {
            const uint32_t ko = ks * 32;  // bytes
            uint32_t ah[2][4], al[2][4], bhf[2][4], blf[2][4];
            LDSM4(ah[0], ah_base + ko);
            LDSM4(ah[1], ah_base + 16 * APAD * 2 + ko);
            LDSM4(al[0], al_base + ko);
            LDSM4(al[1], al_base + 16 * APAD * 2 + ko);
            LDSM4(bhf[0], bh_base + ko);
            LDSM4(bhf[1], bh_base + 16 * APAD * 2 + ko);
            LDSM4(blf[0], bl_base + ko);
            LDSM4(blf[1], bl_base + 16 * APAD * 2 + ko);
            #pragma unroll
            for (int mi = 0; mi < 2; mi++) {
                #pragma unroll
                for (int p = 0; p < 2; p++) {
                    #pragma unroll
                    for (int q = 0; q < 2; q++) {
                        const int nf = p * 2 + q;
                        MMA16816(c[mi][nf], ah[mi], bhf[p][q * 2], bhf[p][q * 2 + 1]);
                        MMA16816(c[mi][nf], al[mi], bhf[p][q * 2], bhf[p][q * 2 + 1]);
                        MMA16816(c[mi][nf], ah[mi], blf[p][q * 2], blf[p][q * 2 + 1]);
                    }
                }
            }
        }
        __syncthreads();

        if (!last) {
            uint32_t hi[8], lo[8];
            #pragma unroll
            for (int p = 0; p < 4; p++) {
                float e0 = fA[p].x, o0 = fA[p].y, e1 = fA[p].z, o1 = fA[p].w;
                uint32_t h0, h1;
                CVT_BF16X2(h0, e0, o0);
                CVT_BF16X2(h1, e1, o1);
                hi[p * 2] = h0; hi[p * 2 + 1] = h1;
                float r0e = e0 - __uint_as_float(h0 << 16);
                float r0o = o0 - __uint_as_float(h0 & 0xffff0000u);
                float r1e = e1 - __uint_as_float(h1 << 16);
                float r1o = o1 - __uint_as_float(h1 & 0xffff0000u);
                uint32_t l0, l1;
                CVT_BF16X2(l0, r0e, r0o);
                CVT_BF16X2(l1, r1e, r1o);
                lo[p * 2] = l0; lo[p * 2 + 1] = l1;
            }
            *(uint4*)&Ah[arow][aseg * 16]     = make_uint4(hi[0], hi[1], hi[2], hi[3]);
            *(uint4*)&Ah[arow][aseg * 16 + 8] = make_uint4(hi[4], hi[5], hi[6], hi[7]);
            *(uint4*)&Al[arow][aseg * 16]     = make_uint4(lo[0], lo[1], lo[2], lo[3]);
            *(uint4*)&Al[arow][aseg * 16 + 8] = make_uint4(lo[4], lo[5], lo[6], lo[7]);
            *(uint4*)&Bh[brow][bseg * 8] = sBh;
            *(uint4*)&Bl[brow][bseg * 8] = sBl;
            __syncthreads();
        }
    }

    // ---- epilogue: write part ----
    float* P = part + (size_t)r * NH;
    #pragma unroll
    for (int mi = 0; mi < 2; mi++) {
        const int rbase = n0 + warp_m * 32 + mi * 16 + (lane >> 2);
        #pragma unroll
        for (int nf = 0; nf < 4; nf++) {
            const int cbase = warp_n * 32 + nf * 8 + (lane & 3) * 2;
            *(float2*)&P[(size_t)rbase * HIDDEN + cbase] =
                make_float2(c[mi][nf][0], c[mi][nf][1]);
            *(float2*)&P[(size_t)(rbase + 8) * HIDDEN + cbase] =
                make_float2(c[mi][nf][2], c[mi][nf][3]);
        }
    }
}

// ---------------------------------------------------------------- finish
__global__ void finish_kernel(const float* __restrict__ S,
                              const float* __restrict__ part,
                              float* __restrict__ hn)
{
    int i = blockIdx.x * blockDim.x + threadIdx.x;
    if (i < NH) {
        float v = S[i];
        #pragma unroll
        for (int r = 0; r < N_REL; r++) v += part[(size_t)r * NH + i];
        hn[i] = fmaxf(v, 0.f);
    }
}

// ---------------------------------------------------------------- gather
__global__ void gather_kernel(const float* __restrict__ h,
                              const int* __restrict__ ids,
                              float* __restrict__ out)
{
    int k = blockIdx.x;
    int e = threadIdx.x;
    int id = ids[k];
    float v = (id < N_NODES) ? h[(size_t)id * HIDDEN + e] : 0.f;
    out[(size_t)k * HIDDEN + e] = v;
}

// ----------------------------------------------------------------
extern "C" void kernel_launch(void* const* d_in, const int* in_sizes, int n_in,
                              void* d_out, int out_size)
{
    const float* node_embed  = (const float*)d_in[0];
    const float* w_self      = (const float*)d_in[1];
    const float* w_rel       = (const float*)d_in[2];
    const float* rel_adj     = (const float*)d_in[3];
    const int*   keyword_ids = (const int*)d_in[4];
    float* out = (float*)d_out;

    float *h_base, *s_base, *p_base;
    __nv_bfloat16 *yh_base, *yl_base;
    cudaGetSymbolAddress((void**)&h_base, g_h);
    cudaGetSymbolAddress((void**)&s_base, g_S);
    cudaGetSymbolAddress((void**)&p_base, g_part);
    cudaGetSymbolAddress((void**)&yh_base, g_Yth);
    cudaGetSymbolAddress((void**)&yl_base, g_Ytl);

    copy_init_kernel<<<NH / 4 / 256, 256>>>(h_base, node_embed);

    for (int l = 0; l < N_LAYERS; l++) {
        float* hc = h_base + (size_t)(l & 1) * NH;
        float* hn = h_base + (size_t)((l + 1) & 1) * NH;
        compute_ys_kernel<<<dim3(64, 9), 256>>>(hc, w_self, w_rel, l, yh_base, yl_base, s_base);
        gemm_mma_kernel<<<dim3(32, N_REL), 256>>>(rel_adj, yh_base, yl_base, p_base);
        finish_kernel<<<NH / 256, 256>>>(s_base, p_base, hn);
    }

    gather_kernel<<<2048, 64>>>(h_base, keyword_ids, out);
}

// round 5
// speedup vs baseline: 2.9263x; 1.0143x over previous
#include <cuda_runtime.h>
#include <cuda_bf16.h>
#include <cstdint>

#define N_NODES 4096
#define HIDDEN  64
#define N_REL   8
#define N_LAYERS 2
#define NH (N_NODES * HIDDEN)

// ---------------------------------------------------------------- helpers
__device__ __forceinline__ uint32_t smem_u32(const void* p) {
    uint32_t a;
    asm("{ .reg .u64 t; cvta.to.shared.u64 t, %1; cvt.u32.u64 %0, t; }" : "=r"(a) : "l"(p));
    return a;
}

// pack two floats into bf16x2 (f_even -> low half)
#define CVT_BF16X2(d, f_even, f_odd) \
    asm("cvt.rn.bf16x2.f32 %0, %1, %2;" : "=r"(d) : "f"(f_odd), "f"(f_even))

#define LDSM4(r, addr) \
    asm volatile("ldmatrix.sync.aligned.m8n8.x4.shared.b16 {%0,%1,%2,%3}, [%4];" \
        : "=r"((r)[0]), "=r"((r)[1]), "=r"((r)[2]), "=r"((r)[3]) : "r"(addr))

#define MMA16816(c, a, b0, b1) \
    asm volatile("mma.sync.aligned.m16n8k16.row.col.f32.bf16.bf16.f32 " \
        "{%0,%1,%2,%3}, {%4,%5,%6,%7}, {%8,%9}, {%0,%1,%2,%3};" \
        : "+f"((c)[0]), "+f"((c)[1]), "+f"((c)[2]), "+f"((c)[3]) \
        : "r"((a)[0]), "r"((a)[1]), "r"((a)[2]), "r"((a)[3]), "r"(b0), "r"(b1))

#define LDGSTS16(dst, src) \
    asm volatile("cp.async.cg.shared.global [%0], [%1], 16;" :: "r"(dst), "l"(src))
#define CP_COMMIT() asm volatile("cp.async.commit_group;" ::: "memory")
#define CP_WAIT1() asm volatile("cp.async.wait_group 1;" ::: "memory")
#define CP_WAIT0() asm volatile("cp.async.wait_group 0;" ::: "memory")

// ---------------------------------------------------------------- scratch
__device__ float g_h[2][NH];
__device__ float g_S[NH];
__device__ float g_part[N_REL][NH];
__device__ __nv_bfloat16 g_Yth[N_REL][HIDDEN][N_NODES];   // Y^T hi  [r][e][m]
__device__ __nv_bfloat16 g_Ytl[N_REL][HIDDEN][N_NODES];   // Y^T lo
__device__ __nv_bfloat16 g_Ah[(size_t)N_REL * N_NODES * N_NODES];  // adj hi limb
__device__ __nv_bfloat16 g_Al[(size_t)N_REL * N_NODES * N_NODES];  // adj lo limb

// ---------------------------------------------------------------- init copy
__global__ void copy_init_kernel(float* __restrict__ dst, const float* __restrict__ src) {
    int i = blockIdx.x * blockDim.x + threadIdx.x;
    if (i < NH / 4) ((float4*)dst)[i] = ((const float4*)src)[i];
}

// ---------------------------------------------------------------- adj -> bf16 hi/lo (ONCE)
__global__ void __launch_bounds__(256) convert_adj_kernel(
    const float* __restrict__ adj,
    __nv_bfloat16* __restrict__ Ah,
    __nv_bfloat16* __restrict__ Al)
{
    size_t i = ((size_t)blockIdx.x * 256 + threadIdx.x) * 8;
    float4 f0 = *(const float4*)(adj + i);
    float4 f1 = *(const float4*)(adj + i + 4);
    uint32_t hi[4], lo[4];
    float e[4] = {f0.x, f0.z, f1.x, f1.z};
    float o[4] = {f0.y, f0.w, f1.y, f1.w};
    #pragma unroll
    for (int p = 0; p < 4; p++) {
        uint32_t h;
        CVT_BF16X2(h, e[p], o[p]);
        hi[p] = h;
        float re = e[p] - __uint_as_float(h << 16);
        float ro = o[p] - __uint_as_float(h & 0xffff0000u);
        CVT_BF16X2(lo[p], re, ro);
    }
    *(uint4*)(Ah + i) = make_uint4(hi[0], hi[1], hi[2], hi[3]);
    *(uint4*)(Al + i) = make_uint4(lo[0], lo[1], lo[2], lo[3]);
}

// ---------------------------------------------------------------- Y / S
__global__ void __launch_bounds__(256) compute_ys_kernel(
    const float* __restrict__ h,
    const float* __restrict__ w_self,
    const float* __restrict__ w_rel,
    int layer,
    __nv_bfloat16* __restrict__ Yth,
    __nv_bfloat16* __restrict__ Ytl,
    float* __restrict__ S)
{
    __shared__ float Ws[HIDDEN * HIDDEN];
    __shared__ float Hs[64 * HIDDEN];

    int m0 = blockIdx.x * 64;
    int wi = blockIdx.y;
    const float* W = (wi < N_REL)
        ? (w_rel + ((size_t)layer * N_REL + wi) * HIDDEN * HIDDEN)
        : (w_self + (size_t)layer * HIDDEN * HIDDEN);

    int tid = threadIdx.x;
    const float4* Wg = (const float4*)W;
    const float4* Hg = (const float4*)(h + (size_t)m0 * HIDDEN);
    for (int i = tid; i < 1024; i += 256) {
        ((float4*)Ws)[i] = Wg[i];
        ((float4*)Hs)[i] = Hg[i];
    }
    __syncthreads();

    int tx = tid & 15, ty = tid >> 4;
    int e0 = tx * 4;
    #pragma unroll
    for (int mi = 0; mi < 4; mi++) {
        int m = ty * 4 + mi;
        float4 acc = make_float4(0.f, 0.f, 0.f, 0.f);
        #pragma unroll
        for (int d = 0; d < HIDDEN; d++) {
            float hv = Hs[m * HIDDEN + d];
            float4 wv = *(const float4*)&Ws[d * HIDDEN + e0];
            acc.x = fmaf(hv, wv.x, acc.x);
            acc.y = fmaf(hv, wv.y, acc.y);
            acc.z = fmaf(hv, wv.z, acc.z);
            acc.w = fmaf(hv, wv.w, acc.w);
        }
        int mg = m0 + m;
        if (wi < N_REL) {
            float v[4] = {acc.x, acc.y, acc.z, acc.w};
            #pragma unroll
            for (int j = 0; j < 4; j++) {
                size_t idx = ((size_t)wi * HIDDEN + (e0 + j)) * N_NODES + mg;
                __nv_bfloat16 hi = __float2bfloat16_rn(v[j]);
                float res = v[j] - __bfloat162float(hi);
                Yth[idx] = hi;
                Ytl[idx] = __float2bfloat16_rn(res);
            }
        } else {
            *(float4*)&S[(size_t)mg * HIDDEN + e0] = acc;
        }
    }
}

// ---------------------------------------------------------------- pipelined tensor GEMM
// part[r][n][e] = sum_m adj[r][n][m] * Y_r[m][e]
// CTA 128(M) x 64(N), KC=64, 2-stage cp.async double buffer, XOR-swizzled smem.
// Stage layout (48 KB): Ah[128][64]bf16 @0, Al @16384, Bh[64][64] @32768, Bl @40960.
#define STAGE_BYTES 49152

__device__ __forceinline__ void load_stage(
    uint32_t sbase, int stage, int mt, int tid,
    const __nv_bfloat16* Ahg, const __nv_bfloat16* Alg,
    const __nv_bfloat16* Bhg, const __nv_bfloat16* Blg)
{
    const uint32_t st = sbase + stage * STAGE_BYTES;
    #pragma unroll
    for (int i = 0; i < 4; i++) {
        int c = tid + i * 256;
        int row = c >> 3, ch = c & 7;
        uint32_t dst = st + row * 128 + (((uint32_t)(ch ^ (row & 7))) << 4);
        size_t src = (size_t)row * N_NODES + mt + ch * 8;
        LDGSTS16(dst,         Ahg + src);
        LDGSTS16(dst + 16384, Alg + src);
    }
    #pragma unroll
    for (int i = 0; i < 2; i++) {
        int c = tid + i * 256;
        int row = c >> 3, ch = c & 7;
        uint32_t dst = st + 32768 + row * 128 + (((uint32_t)(ch ^ (row & 7))) << 4);
        size_t src = (size_t)row * N_NODES + mt + ch * 8;
        LDGSTS16(dst,        Bhg + src);
        LDGSTS16(dst + 8192, Blg + src);
    }
}

__global__ void __launch_bounds__(256, 2) gemm_pipe_kernel(
    const __nv_bfloat16* __restrict__ Ahg_all,
    const __nv_bfloat16* __restrict__ Alg_all,
    const __nv_bfloat16* __restrict__ Yth,
    const __nv_bfloat16* __restrict__ Ytl,
    float* __restrict__ part)
{
    extern __shared__ __align__(16) char smem[];
    const int tid  = threadIdx.x;
    const int lane = tid & 31;
    const int wid  = tid >> 5;
    const int warp_m = wid & 3;
    const int warp_n = wid >> 2;
    const int n0 = blockIdx.x * 128;
    const int r  = blockIdx.y;
    const uint32_t sbase = smem_u32(smem);

    // per-CTA gmem bases
    const __nv_bfloat16* Ahg = Ahg_all + ((size_t)r * N_NODES + n0) * N_NODES;
    const __nv_bfloat16* Alg = Alg_all + ((size_t)r * N_NODES + n0) * N_NODES;
    const __nv_bfloat16* Bhg = Yth + (size_t)r * HIDDEN * N_NODES;
    const __nv_bfloat16* Blg = Ytl + (size_t)r * HIDDEN * N_NODES;

    // ldmatrix lane geometry (identical logical mapping to round-4 kernel)
    const int a_r  = warp_m * 32 + (lane & 15);
    const int a_hi = lane >> 4;                       // chunk lsb
    const int a_s7 = a_r & 7;
    const uint32_t aRow = (uint32_t)(a_r * 128);
    const int b_r  = warp_n * 32 + (lane & 7) + ((lane >> 4) & 1) * 8;
    const int b_k  = (lane >> 3) & 1;
    const int b_s7 = b_r & 7;
    const uint32_t bRow = (uint32_t)(b_r * 128);

    float c[2][4][4];
    #pragma unroll
    for (int i = 0; i < 2; i++)
        #pragma unroll
        for (int j = 0; j < 4; j++)
            #pragma unroll
            for (int k = 0; k < 4; k++) c[i][j][k] = 0.f;

    // prologue
    load_stage(sbase, 0, 0, tid, Ahg, Alg, Bhg, Blg);
    CP_COMMIT();

    #pragma unroll 1
    for (int it = 0; it < N_NODES / 64; ++it) {
        const int buf = it & 1;
        if (it < N_NODES / 64 - 1) {
            load_stage(sbase, buf ^ 1, (it + 1) * 64, tid, Ahg, Alg, Bhg, Blg);
            CP_COMMIT();
            CP_WAIT1();
        } else {
            CP_WAIT0();
        }
        __syncthreads();

        const uint32_t st = sbase + buf * STAGE_BYTES;
        #pragma unroll
        for (int ks = 0; ks < 4; ks++) {
            const uint32_t aoff = ((uint32_t)((ks * 2 + a_hi) ^ a_s7)) << 4;
            const uint32_t boff = ((uint32_t)((ks * 2 + b_k) ^ b_s7)) << 4;
            uint32_t ah[2][4], al[2][4], bh[2][4], bl[2][4];
            LDSM4(ah[0], st + aRow + aoff);
            LDSM4(ah[1], st + aRow + 2048 + aoff);
            LDSM4(al[0], st + 16384 + aRow + aoff);
            LDSM4(al[1], st + 16384 + aRow + 2048 + aoff);
            LDSM4(bh[0], st + 32768 + bRow + boff);
            LDSM4(bh[1], st + 32768 + bRow + 2048 + boff);
            LDSM4(bl[0], st + 40960 + bRow + boff);
            LDSM4(bl[1], st + 40960 + bRow + 2048 + boff);
            #pragma unroll
            for (int mi = 0; mi < 2; mi++) {
                #pragma unroll
                for (int p = 0; p < 2; p++) {
                    #pragma unroll
                    for (int q = 0; q < 2; q++) {
                        const int nf = p * 2 + q;
                        MMA16816(c[mi][nf], ah[mi], bh[p][q * 2], bh[p][q * 2 + 1]);
                        MMA16816(c[mi][nf], al[mi], bh[p][q * 2], bh[p][q * 2 + 1]);
                        MMA16816(c[mi][nf], ah[mi], bl[p][q * 2], bl[p][q * 2 + 1]);
                    }
                }
            }
        }
        __syncthreads();
    }

    // epilogue
    float* P = part + (size_t)r * NH;
    #pragma unroll
    for (int mi = 0; mi < 2; mi++) {
        const int rbase = n0 + warp_m * 32 + mi * 16 + (lane >> 2);
        #pragma unroll
        for (int nf = 0; nf < 4; nf++) {
            const int cbase = warp_n * 32 + nf * 8 + (lane & 3) * 2;
            *(float2*)&P[(size_t)rbase * HIDDEN + cbase] =
                make_float2(c[mi][nf][0], c[mi][nf][1]);
            *(float2*)&P[(size_t)(rbase + 8) * HIDDEN + cbase] =
                make_float2(c[mi][nf][2], c[mi][nf][3]);
        }
    }
}

// ---------------------------------------------------------------- finish
__global__ void finish_kernel(const float* __restrict__ S,
                              const float* __restrict__ part,
                              float* __restrict__ hn)
{
    int i = blockIdx.x * blockDim.x + threadIdx.x;
    if (i < NH) {
        float v = S[i];
        #pragma unroll
        for (int r = 0; r < N_REL; r++) v += part[(size_t)r * NH + i];
        hn[i] = fmaxf(v, 0.f);
    }
}

// ---------------------------------------------------------------- gather
__global__ void gather_kernel(const float* __restrict__ h,
                              const int* __restrict__ ids,
                              float* __restrict__ out)
{
    int k = blockIdx.x;
    int e = threadIdx.x;
    int id = ids[k];
    float v = (id < N_NODES) ? h[(size_t)id * HIDDEN + e] : 0.f;
    out[(size_t)k * HIDDEN + e] = v;
}

// ----------------------------------------------------------------
extern "C" void kernel_launch(void* const* d_in, const int* in_sizes, int n_in,
                              void* d_out, int out_size)
{
    const float* node_embed  = (const float*)d_in[0];
    const float* w_self      = (const float*)d_in[1];
    const float* w_rel       = (const float*)d_in[2];
    const float* rel_adj     = (const float*)d_in[3];
    const int*   keyword_ids = (const int*)d_in[4];
    float* out = (float*)d_out;

    float *h_base, *s_base, *p_base;
    __nv_bfloat16 *yh_base, *yl_base, *ah_base, *al_base;
    cudaGetSymbolAddress((void**)&h_base, g_h);
    cudaGetSymbolAddress((void**)&s_base, g_S);
    cudaGetSymbolAddress((void**)&p_base, g_part);
    cudaGetSymbolAddress((void**)&yh_base, g_Yth);
    cudaGetSymbolAddress((void**)&yl_base, g_Ytl);
    cudaGetSymbolAddress((void**)&ah_base, g_Ah);
    cudaGetSymbolAddress((void**)&al_base, g_Al);

    static bool attr_set = false;
    if (!attr_set) {
        cudaFuncSetAttribute(gemm_pipe_kernel,
                             cudaFuncAttributeMaxDynamicSharedMemorySize, 2 * STAGE_BYTES);
        attr_set = true;
    }

    copy_init_kernel<<<NH / 4 / 256, 256>>>(h_base, node_embed);
    convert_adj_kernel<<<65536, 256>>>(rel_adj, ah_base, al_base);

    for (int l = 0; l < N_LAYERS; l++) {
        float* hc = h_base + (size_t)(l & 1) * NH;
        float* hn = h_base + (size_t)((l + 1) & 1) * NH;
        compute_ys_kernel<<<dim3(64, 9), 256>>>(hc, w_self, w_rel, l, yh_base, yl_base, s_base);
        gemm_pipe_kernel<<<dim3(32, N_REL), 256, 2 * STAGE_BYTES>>>(
            ah_base, al_base, yh_base, yl_base, p_base);
        finish_kernel<<<NH / 256, 256>>>(s_base, p_base, hn);
    }

    gather_kernel<<<2048, 64>>>(h_base, keyword_ids, out);
}